// round 4
// baseline (speedup 1.0000x reference)
#include <cuda_runtime.h>

// x:(T,B,NI) W1:(NH,NI) b1:(NH) W2:(NO,NH) b2:(NO)
// out = concat(spk1[T,B,NH], mem1[T,B,NH], spk2[T,B,NO], mem2[T,B,NO])
#define T_STEPS 100
#define BATCH   65536
#define NI      2
#define NH      10
#define NO      4
#define BETA    0.5f
#define THRV    1.0f

#define BLOCK_THREADS 64
#define WARPS_PER_BLOCK (BLOCK_THREADS / 32)

// Per-warp staging: [spk1: 320 floats][mem1: 320 floats], double buffered.
// Layout inside each segment is b-major: element (lane, h) at lane*NH + h,
// IDENTICAL to the global layout, so the cooperative copy is a straight memcpy.
#define WARP_SEG   (32 * NH)        // 320 floats
#define WARP_BUF   (2 * WARP_SEG)   // 640 floats

__global__ __launch_bounds__(BLOCK_THREADS) void snn_kernel(
    const float* __restrict__ x,
    const float* __restrict__ W1,
    const float* __restrict__ b1,
    const float* __restrict__ W2,
    const float* __restrict__ b2,
    float* __restrict__ out)
{
    __shared__ float sm[WARPS_PER_BLOCK][2][WARP_BUF];

    const int tid  = threadIdx.x;
    const int wid  = tid >> 5;
    const int lane = tid & 31;
    const int b    = blockIdx.x * BLOCK_THREADS + tid;
    const int b0w  = blockIdx.x * BLOCK_THREADS + wid * 32;  // warp's first batch

    // ---- weights into registers ----
    float w1a[NH], w1b[NH], bb1[NH];
#pragma unroll
    for (int h = 0; h < NH; h++) {
        w1a[h] = __ldg(W1 + h * NI + 0);
        w1b[h] = __ldg(W1 + h * NI + 1);
        bb1[h] = __ldg(b1 + h);
    }
    float w2[NO][NH], bb2[NO];
#pragma unroll
    for (int o = 0; o < NO; o++) {
        bb2[o] = __ldg(b2 + o);
#pragma unroll
        for (int h = 0; h < NH; h++) w2[o][h] = __ldg(W2 + o * NH + h);
    }

    // ---- state ----
    float mem1[NH];
    float mem2[NO];
#pragma unroll
    for (int h = 0; h < NH; h++) mem1[h] = 0.0f;
#pragma unroll
    for (int o = 0; o < NO; o++) mem2[o] = 0.0f;

    // ---- output bases ----
    float* const oSpk1 = out;
    float* const oMem1 = out + (size_t)T_STEPS * BATCH * NH;
    float* const oSpk2 = out + (size_t)2 * T_STEPS * BATCH * NH;
    float* const oMem2 = oSpk2 + (size_t)T_STEPS * BATCH * NO;

    const float2* __restrict__ xp = reinterpret_cast<const float2*>(x);

    // 2-deep x prefetch (streaming loads; no reuse)
    float2 xv  = __ldcs(&xp[(size_t)0 * BATCH + b]);
    float2 xv1 = __ldcs(&xp[(size_t)1 * BATCH + b]);

    for (int t = 0; t < T_STEPS; t++) {
        const int tpf = (t + 2 < T_STEPS) ? (t + 2) : (T_STEPS - 1);
        float2 xnext = __ldcs(&xp[(size_t)tpf * BATCH + b]);

        const float x0 = xv.x, x1 = xv.y;
        float* const buf = sm[wid][t & 1];

        // ---- layer 1 LIF ----
        float spk1[NH];
#pragma unroll
        for (int h = 0; h < NH; h++) {
            float syn   = fmaf(x0, w1a[h], fmaf(x1, w1b[h], bb1[h]));
            float reset = (mem1[h] > THRV) ? THRV : 0.0f;
            float m     = fmaf(BETA, mem1[h], syn) - reset;
            mem1[h]     = m;
            spk1[h]     = (m > THRV) ? 1.0f : 0.0f;
        }
        // stage to smem in b-major order (matches global layout)
        {
            float2* ps = reinterpret_cast<float2*>(buf + lane * NH);
            float2* pm = reinterpret_cast<float2*>(buf + WARP_SEG + lane * NH);
#pragma unroll
            for (int i = 0; i < NH / 2; i++) {
                ps[i] = make_float2(spk1[2 * i], spk1[2 * i + 1]);
                pm[i] = make_float2(mem1[2 * i], mem1[2 * i + 1]);
            }
        }

        // ---- layer 2 LIF -> direct coalesced float4 streaming stores ----
        float spk2[NO];
#pragma unroll
        for (int o = 0; o < NO; o++) {
            float syn = bb2[o];
#pragma unroll
            for (int h = 0; h < NH; h++) syn = fmaf(spk1[h], w2[o][h], syn);
            float reset = (mem2[o] > THRV) ? THRV : 0.0f;
            float m     = fmaf(BETA, mem2[o], syn) - reset;
            mem2[o]     = m;
            spk2[o]     = (m > THRV) ? 1.0f : 0.0f;
        }
        {
            const size_t off = (size_t)t * BATCH * NO + (size_t)b * NO;
            __stcs(reinterpret_cast<float4*>(oSpk2 + off),
                   make_float4(spk2[0], spk2[1], spk2[2], spk2[3]));
            __stcs(reinterpret_cast<float4*>(oMem2 + off),
                   make_float4(mem2[0], mem2[1], mem2[2], mem2[3]));
        }

        __syncwarp();

        // ---- warp-cooperative coalesced stores of spk1/mem1 ----
        // buf = 640 floats = 160 float4: [0,80) -> spk1 region, [80,160) -> mem1.
        {
            const float4* s4 = reinterpret_cast<const float4*>(buf);
            const size_t g1 = (size_t)t * BATCH * NH + (size_t)b0w * NH;
            float4* gs = reinterpret_cast<float4*>(oSpk1 + g1);
            float4* gm = reinterpret_cast<float4*>(oMem1 + g1);
#pragma unroll
            for (int k = 0; k < 5; k++) {
                const int i = lane + k * 32;
                const float4 v = s4[i];
                if (i < 80) __stcs(&gs[i], v);
                else        __stcs(&gm[i - 80], v);
            }
        }
        // double-buffered: next write to this buffer is after the next syncwarp

        xv  = xv1;
        xv1 = xnext;
    }
}

extern "C" void kernel_launch(void* const* d_in, const int* in_sizes, int n_in,
                              void* d_out, int out_size) {
    const float* x  = (const float*)d_in[0];
    const float* W1 = (const float*)d_in[1];
    const float* b1 = (const float*)d_in[2];
    const float* W2 = (const float*)d_in[3];
    const float* b2 = (const float*)d_in[4];
    float* out = (float*)d_out;

    snn_kernel<<<BATCH / BLOCK_THREADS, BLOCK_THREADS>>>(x, W1, b1, W2, b2, out);
}